// round 17
// baseline (speedup 1.0000x reference)
#include <cuda_runtime.h>
#include <cuda_bf16.h>
#include <cstdint>
#include <cmath>

// ---------------------------------------------------------------------------
// Problem constants
// ---------------------------------------------------------------------------
#define NROWS 2048
#define NFEAT 128
#define TILE  128
#define PREP_BLOCKS 256           // 8 rows per block
#define NPAIRS 136                // upper-triangle 16x16 tiles (bi <= bj)
#define NHALF  272                // two 128x64 half-tiles per pair
#define MAIN_CTAS 280             // 272 half-tiles + 8 sigma reducers

// ---------------------------------------------------------------------------
// Device scratch (zero-initialized; no allocation allowed)
// ---------------------------------------------------------------------------
__device__ __nv_bfloat16 g_Xb[NROWS * NFEAT];        // bf16-quantized X
__device__ float g_norm[NROWS];                      // row norms of quantized X
__device__ float g_s_part[PREP_BLOCKS][NFEAT];       // per-block feature sums
__device__ float g_sumn_part[PREP_BLOCKS];           // per-block norm sums
__device__ float g_s2[8][NFEAT];                     // level-2 feature sums
__device__ float g_sn2[8];                           // level-2 norm sums
__device__ float g_c;                                // inv2s * log2(e)
__device__ int   g_ctr3;                             // sigma level-2 counter
__device__ int   g_ctr2;                             // exit counter
__device__ int   g_flag2;                            // sigma ready

// ---------------------------------------------------------------------------
// Helpers
// ---------------------------------------------------------------------------
__device__ __forceinline__ uint32_t smem_to_u32(const void* p) {
    uint32_t a;
    asm("{ .reg .u64 t; cvta.to.shared.u64 t, %1; cvt.u32.u64 %0, t; }" : "=r"(a) : "l"(p));
    return a;
}

__device__ __forceinline__ void ldmatrix_x4(uint32_t& r0, uint32_t& r1,
                                            uint32_t& r2, uint32_t& r3, uint32_t addr) {
    asm volatile("ldmatrix.sync.aligned.m8n8.x4.shared.b16 {%0,%1,%2,%3}, [%4];"
                 : "=r"(r0), "=r"(r1), "=r"(r2), "=r"(r3) : "r"(addr));
}

__device__ __forceinline__ void mma_16816(float* d, const uint32_t* a, const uint32_t* b) {
    asm volatile(
        "mma.sync.aligned.m16n8k16.row.col.f32.bf16.bf16.f32 "
        "{%0,%1,%2,%3}, {%4,%5,%6,%7}, {%8,%9}, {%0,%1,%2,%3};"
        : "+f"(d[0]), "+f"(d[1]), "+f"(d[2]), "+f"(d[3])
        : "r"(a[0]), "r"(a[1]), "r"(a[2]), "r"(a[3]), "r"(b[0]), "r"(b[1]));
}

__device__ __forceinline__ float ex2f(float x) {
    float r;
    asm("ex2.approx.ftz.f32 %0, %1;" : "=f"(r) : "f"(x));
    return r;
}

__device__ __forceinline__ void spin_until(volatile int* fp) {
    while (*fp == 0) { __nanosleep(32); }
}

// ---------------------------------------------------------------------------
// Kernel 1: prep. grid 256, block 256; block handles 8 rows.
// ---------------------------------------------------------------------------
__global__ void __launch_bounds__(256) prep_kernel(const float* __restrict__ X) {
    int b   = blockIdx.x;
    int tid = threadIdx.x;
    int wid = tid >> 5;
    int lid = tid & 31;

    __shared__ float ss[8][NFEAT];
    __shared__ float sn[8];

    {
        int row = b * 8 + wid;
        float4 v = reinterpret_cast<const float4*>(X + (size_t)row * NFEAT)[lid];
        __nv_bfloat16 b0 = __float2bfloat16(v.x);
        __nv_bfloat16 b1 = __float2bfloat16(v.y);
        __nv_bfloat16 b2 = __float2bfloat16(v.z);
        __nv_bfloat16 b3 = __float2bfloat16(v.w);
        __nv_bfloat162* dst =
            reinterpret_cast<__nv_bfloat162*>(g_Xb + (size_t)row * NFEAT) + lid * 2;
        dst[0] = __nv_bfloat162(b0, b1);
        dst[1] = __nv_bfloat162(b2, b3);
        // quantized values downstream (diag exactly 0 -> out = 1)
        float fx = __bfloat162float(b0), fy = __bfloat162float(b1);
        float fz = __bfloat162float(b2), fw = __bfloat162float(b3);
        float sq = fx * fx + fy * fy + fz * fz + fw * fw;
        #pragma unroll
        for (int o = 16; o > 0; o >>= 1) sq += __shfl_xor_sync(0xFFFFFFFFu, sq, o);
        if (lid == 0) { g_norm[row] = sq; sn[wid] = sq; }
        ss[wid][lid * 4 + 0] = fx;
        ss[wid][lid * 4 + 1] = fy;
        ss[wid][lid * 4 + 2] = fz;
        ss[wid][lid * 4 + 3] = fw;
    }
    __syncthreads();
    if (tid < NFEAT) {
        float t = 0.f;
        #pragma unroll
        for (int w = 0; w < 8; w++) t += ss[w][tid];
        g_s_part[b][tid] = t;
    }
    if (tid == 0) {
        float t = 0.f;
        #pragma unroll
        for (int w = 0; w < 8; w++) t += sn[w];
        g_sumn_part[b] = t;
    }
}

// ---------------------------------------------------------------------------
// Kernel 2: main. grid 280 x 256 threads, 2 CTAs/SM, single wave.
//   b <  272 : half-tile CTA. pair p = b>>1 -> (bi<=bj); half h = b&1 ->
//              cols [bj*128 + h*64, +64). Computes 128x64, stores direct;
//              off-diagonal pairs also store the transposed 64x128 block.
//   b >= 272 : sigma reducer CTA (8): reduce -> flag2 -> exit.
// ---------------------------------------------------------------------------
#define OFF_CI  0
#define OFF_CJ  512
#define OFF_FS  1024
#define OFF_A   2048
#define OFF_B   (OFF_A + 32768)
#define OFF_STG OFF_A                       // staging reuses A/B after MMA
#define STG_PAD 132                         // words per staged column-row
#define SMEM_TOTAL (OFF_B + 16384)          // 51200 B -> 2 CTAs/SM

__global__ void __launch_bounds__(256, 2) gauss_main_kernel(float* __restrict__ out) {
    extern __shared__ char smem[];
    uint32_t sb = smem_to_u32(smem);
    int b   = blockIdx.x;
    int tid = threadIdx.x;
    int wid = tid >> 5;
    int lid = tid & 31;

    __shared__ float red[5];
    __shared__ int   s_last3;

    // =============== Sigma reducer CTAs (b >= 272): reduce and exit ========
    if (b >= NHALF) {
        int b2 = b - NHALF;                                    // 0..7
        float* ss2 = reinterpret_cast<float*>(smem + OFF_FS);  // [2][128]
        {
            int f = tid & 127;
            int g = tid >> 7;
            float sf = 0.f;
            #pragma unroll 16
            for (int p = b2 * 32 + g * 16; p < b2 * 32 + g * 16 + 16; p++)
                sf += g_s_part[p][f];
            ss2[g * NFEAT + f] = sf;
        }
        if (tid < 32) {
            float sna = g_sumn_part[b2 * 32 + tid];
            #pragma unroll
            for (int o = 16; o > 0; o >>= 1) sna += __shfl_xor_sync(0xFFFFFFFFu, sna, o);
            if (tid == 0) g_sn2[b2] = sna;
        }
        __syncthreads();
        if (tid < NFEAT)
            ((float*)0, g_s2[b2][tid] = ss2[tid] + ss2[NFEAT + tid]);
        __threadfence();
        __syncthreads();
        if (tid == 0) s_last3 = (atomicAdd(&g_ctr3, 1) == 7) ? 1 : 0;
        __syncthreads();
        if (s_last3) {
            if (tid < NFEAT) {
                float s = 0.f;
                #pragma unroll
                for (int q = 0; q < 8; q++) s += __ldcg(&g_s2[q][tid]);
                float v = s * s;
                #pragma unroll
                for (int o = 16; o > 0; o >>= 1) v += __shfl_xor_sync(0xFFFFFFFFu, v, o);
                if (lid == 0) red[wid] = v;
            }
            if (tid >= 224) {      // warp 7 sums sn2
                float sna = (lid < 8) ? __ldcg(&g_sn2[lid]) : 0.f;
                #pragma unroll
                for (int o = 4; o > 0; o >>= 1) sna += __shfl_xor_sync(0xFFFFFFFFu, sna, o);
                if (lid == 0) red[4] = sna;
            }
            __syncthreads();
            if (tid == 0) {
                float S2   = red[0] + red[1] + red[2] + red[3];
                float sumn = red[4];
                float Nf = (float)NROWS;
                float inv2s = (Nf * Nf) / (4.f * Nf * sumn - 4.f * S2);
                g_c = inv2s * 1.4426950408889634f;   // fold log2(e) for ex2
                __threadfence();
                *((volatile int*)&g_flag2) = 1;
            }
        }
        if (tid == 0) {
            if (atomicAdd(&g_ctr2, 1) == MAIN_CTAS - 1) {
                g_ctr3 = 0; g_ctr2 = 0; g_flag2 = 0;
            }
        }
        return;
    }

    // =============== Half-tile CTA: map b -> (bi, bj, h) ===================
    int p = b >> 1;
    int h = b & 1;
    int bi = (int)(16.5f - sqrtf(16.5f * 16.5f - 2.0f * (float)p));
    while ((bi + 1) * (33 - (bi + 1)) / 2 <= p) bi++;
    while (bi * (33 - bi) / 2 > p) bi--;
    int bj = bi + (p - bi * (33 - bi) / 2);
    bool offdiag = (bi != bj);
    int col0 = bj * TILE + h * 64;            // global first column of half

    // =============== Tile loads: A = 128 rows of bi, B = 64 rows of cols ===
    const uint4* A4 = reinterpret_cast<const uint4*>(g_Xb + (size_t)bi * TILE * NFEAT);
    const uint4* B4 = reinterpret_cast<const uint4*>(g_Xb + (size_t)col0 * NFEAT);
    #pragma unroll
    for (int idx = tid; idx < 2048; idx += 256) {   // A: 128 rows x 16 chunks
        int row = idx >> 4;
        int ch  = idx & 15;
        uint32_t off = (uint32_t)row * 256u + (uint32_t)(ch ^ (row & 7)) * 16u;
        *reinterpret_cast<uint4*>(smem + OFF_A + off) = A4[idx];
    }
    #pragma unroll
    for (int idx = tid; idx < 1024; idx += 256) {   // B: 64 rows x 16 chunks
        int row = idx >> 4;
        int ch  = idx & 15;
        uint32_t off = (uint32_t)row * 256u + (uint32_t)(ch ^ (row & 7)) * 16u;
        *reinterpret_cast<uint4*>(smem + OFF_B + off) = B4[idx];
    }
    // prefetch norms while loads fly
    float n_pref = 0.f;
    if (tid < TILE)            n_pref = g_norm[bi * TILE + tid];
    else if (tid < TILE + 64)  n_pref = g_norm[col0 + (tid - TILE)];
    __syncthreads();

    // =============== per-warp MMA: 4(m) x 2(n) warps, 32x32 each ===========
    int wm  = (wid & 3) * 32;
    int wn2 = (wid >> 2) * 32;

    float d[2][4][4];
    #pragma unroll
    for (int mt = 0; mt < 2; mt++)
        #pragma unroll
        for (int nt = 0; nt < 4; nt++)
            #pragma unroll
            for (int e = 0; e < 4; e++) d[mt][nt][e] = 0.f;

    uint32_t a_row  = (uint32_t)(wm + (lid & 15));
    uint32_t a_cbit = (uint32_t)(lid >> 4);
    uint32_t a_rl   = a_row & 7;
    uint32_t a_base0 = sb + OFF_A + a_row * 256u;
    uint32_t a_base1 = a_base0 + 16u * 256u;

    uint32_t b_row  = (uint32_t)(wn2 + (lid & 7) + ((lid & 16) >> 1));
    uint32_t b_cbit = (uint32_t)((lid >> 3) & 1);
    uint32_t b_rl   = b_row & 7;
    uint32_t b_base0 = sb + OFF_B + b_row * 256u;
    uint32_t b_base1 = b_base0 + 16u * 256u;

    uint32_t af[2][2][4];
    uint32_t bf[2][4][2];

#define LOAD_A(kc, bufi) do {                                                   \
        uint32_t sc = ((uint32_t)(2 * (kc)) + a_cbit) ^ a_rl;                   \
        ldmatrix_x4(af[bufi][0][0], af[bufi][0][1], af[bufi][0][2],             \
                    af[bufi][0][3], a_base0 + (sc << 4));                       \
        ldmatrix_x4(af[bufi][1][0], af[bufi][1][1], af[bufi][1][2],             \
                    af[bufi][1][3], a_base1 + (sc << 4));                       \
    } while (0)

#define LOAD_B(kc, bufi) do {                                                   \
        uint32_t sc = ((uint32_t)(2 * (kc)) + b_cbit) ^ b_rl;                   \
        ldmatrix_x4(bf[bufi][0][0], bf[bufi][0][1], bf[bufi][1][0],             \
                    bf[bufi][1][1], b_base0 + (sc << 4));                       \
        ldmatrix_x4(bf[bufi][2][0], bf[bufi][2][1], bf[bufi][3][0],             \
                    bf[bufi][3][1], b_base1 + (sc << 4));                       \
    } while (0)

    LOAD_A(0, 0);
    LOAD_B(0, 0);
    #pragma unroll
    for (int kc = 0; kc < 8; kc++) {
        int cur = kc & 1, nxt = cur ^ 1;
        if (kc < 7) { LOAD_A(kc + 1, nxt); LOAD_B(kc + 1, nxt); }
        #pragma unroll
        for (int mt = 0; mt < 2; mt++)
            #pragma unroll
            for (int nt = 0; nt < 4; nt++)
                mma_16816(d[mt][nt], af[cur][mt], bf[cur][nt]);
    }
#undef LOAD_A
#undef LOAD_B

    // =============== Wait for sigma (long done by now) ====================
    if (tid == 0) spin_until((volatile int*)&g_flag2);
    __syncthreads();            // also: all LDSM reads of A/B done
    float c = __ldcg(&g_c);

    if (tid < TILE)
        reinterpret_cast<float*>(smem + OFF_CI)[tid] = -n_pref * c;
    else if (tid < TILE + 64)
        reinterpret_cast<float*>(smem + OFF_CJ)[tid - TILE] = -n_pref * c;
    __syncthreads();

    // =============== Epilogue: direct store (+ stage transposed) ==========
    float sc2 = 2.f * c;
    const float* cis = reinterpret_cast<const float*>(smem + OFF_CI);
    const float* cjs = reinterpret_cast<const float*>(smem + OFF_CJ);
    float* stage = reinterpret_cast<float*>(smem + OFF_STG);
    int quad = lid >> 2;
    int qt   = lid & 3;

    #pragma unroll
    for (int mt = 0; mt < 2; mt++) {
        #pragma unroll
        for (int half = 0; half < 2; half++) {
            int r  = wm + mt * 16 + quad + half * 8;
            float ci = cis[r];
            float* orow = out + (size_t)(bi * TILE + r) * NROWS + col0 + wn2;
            #pragma unroll
            for (int nt = 0; nt < 4; nt++) {
                int col = nt * 8 + qt * 2;
                float e0 = fmaf(d[mt][nt][half * 2 + 0], sc2, ci + cjs[wn2 + col]);
                float e1 = fmaf(d[mt][nt][half * 2 + 1], sc2, ci + cjs[wn2 + col + 1]);
                float o0 = ex2f(e0);
                float o1 = ex2f(e1);
                *reinterpret_cast<float2*>(orow + col) = make_float2(o0, o1);
                if (offdiag) {
                    int cc = wn2 + col;
                    stage[(uint32_t)cc * STG_PAD + r]       = o0;   // banks 8qt+quad
                    stage[(uint32_t)(cc + 1) * STG_PAD + r] = o1;
                }
            }
        }
    }

    if (!offdiag) {
        __syncthreads();
        if (tid == 0) {
            if (atomicAdd(&g_ctr2, 1) == MAIN_CTAS - 1) {
                g_ctr3 = 0; g_ctr2 = 0; g_flag2 = 0;
            }
        }
        return;
    }

    // =============== Transposed store: 64 rows x 128 cols =================
    __syncthreads();
    {
        int ct  = tid & 63;          // transposed row (= local col)
        int seg = tid >> 6;          // 0..3, 32 floats each
        const float* srow = stage + (uint32_t)ct * STG_PAD + seg * 32;
        float* drow = out + (size_t)(col0 + ct) * NROWS + bi * TILE + seg * 32;
        #pragma unroll
        for (int q = 0; q < 8; q++) {
            float4 v = *reinterpret_cast<const float4*>(srow + q * 4);
            *reinterpret_cast<float4*>(drow + q * 4) = v;
        }
    }

    __syncthreads();
    if (tid == 0) {
        if (atomicAdd(&g_ctr2, 1) == MAIN_CTAS - 1) {
            g_ctr3 = 0; g_ctr2 = 0; g_flag2 = 0;
        }
    }
}

// ---------------------------------------------------------------------------
// Launch
// ---------------------------------------------------------------------------
extern "C" void kernel_launch(void* const* d_in, const int* in_sizes, int n_in,
                              void* d_out, int out_size) {
    const float* X = (const float*)d_in[0];
    float* out = (float*)d_out;
    (void)in_sizes; (void)n_in; (void)out_size;

    cudaFuncSetAttribute(gauss_main_kernel,
                         cudaFuncAttributeMaxDynamicSharedMemorySize, SMEM_TOTAL);

    prep_kernel<<<PREP_BLOCKS, 256>>>(X);
    gauss_main_kernel<<<MAIN_CTAS, 256, SMEM_TOTAL>>>(out);
}